// round 1
// baseline (speedup 1.0000x reference)
#include <cuda_runtime.h>

// Controlled-SX on qutrits (dim=3, 16 qudits), targets (ctrl=2, obj=5).
// op_im == 0, op_re == identity except ctrl-digit==1 block:
//   d2!=1            : out[i] = in[i]
//   d2==1, d5==0     : out[i] = in[i + 3^10]
//   d2==1, d5==1     : out[i] = in[i - 3^10]
//   d2==1, d5==2     : out[i] = 0
// Applied identically to real and imag planes.

static constexpr int S5 = 59049;    // 3^10  (stride of qudit 5)
static constexpr int S2 = 1594323;  // 3^13  (stride of qudit 2)

__global__ void __launch_bounds__(256)
sx_apply_kernel(const float* __restrict__ in_re,
                const float* __restrict__ in_im,
                float* __restrict__ out_re,
                float* __restrict__ out_im,
                int n)
{
    int i = blockIdx.x * blockDim.x + threadIdx.x;
    if (i >= n) return;

    // digit of qudit 2 (stride 3^13) — constant-divisor div -> IMAD magic mul
    int d2 = (i / S2) % 3;

    float vr, vi;
    if (d2 != 1) {
        // identity region (2/3 of the state)
        vr = __ldg(in_re + i);
        vi = __ldg(in_im + i);
    } else {
        int d5 = (i / S5) % 3;
        if (d5 == 0) {
            vr = __ldg(in_re + i + S5);
            vi = __ldg(in_im + i + S5);
        } else if (d5 == 1) {
            vr = __ldg(in_re + i - S5);
            vi = __ldg(in_im + i - S5);
        } else {
            vr = 0.0f;
            vi = 0.0f;
        }
    }

    out_re[i] = vr;
    out_im[i] = vi;
}

extern "C" void kernel_launch(void* const* d_in, const int* in_sizes, int n_in,
                              void* d_out, int out_size)
{
    const float* in_re = (const float*)d_in[0];
    const float* in_im = (const float*)d_in[1];
    const int n = in_sizes[0];          // 3^16 = 43,046,721

    float* out_re = (float*)d_out;      // output tuple laid out concatenated:
    float* out_im = (float*)d_out + n;  // [out_re (n floats), out_im (n floats)]

    const int threads = 256;
    const int blocks = (n + threads - 1) / threads;
    sx_apply_kernel<<<blocks, threads>>>(in_re, in_im, out_re, out_im, n);
}

// round 3
// speedup vs baseline: 1.4627x; 1.4627x over previous
#include <cuda_runtime.h>

// Controlled-SX on qutrits (dim=3, 16 qudits), ctrl=2, obj=5.
//   d2!=1          : out[i] = in[i]
//   d2==1, d5==0   : out[i] = in[i + 3^10]
//   d2==1, d5==1   : out[i] = in[i - 3^10]
//   d2==1, d5==2   : out[i] = 0
// 1 thread = 1 quad (4 consecutive i). Quads are homogeneous unless they
// straddle a multiple of S5 = 3^10 (rare: 1/14762 quads).
// NOTE: out_im = d_out + n with n odd -> out_im is only 4B-aligned.
// So: vector loads + vector store for re plane, SCALAR stores for im plane.

static constexpr int S5 = 59049;    // 3^10
static constexpr int S2 = 1594323;  // 3^13 = 27 * S5

__device__ __forceinline__ void scalar_one(const float* __restrict__ in_re,
                                           const float* __restrict__ in_im,
                                           float* __restrict__ out_re,
                                           float* __restrict__ out_im,
                                           int idx)
{
    int q5 = idx / S5;
    int d5 = q5 % 3;
    int d2 = (q5 / 27) % 3;
    float vr, vi;
    if (d2 != 1) {
        vr = __ldg(in_re + idx);
        vi = __ldg(in_im + idx);
    } else if (d5 == 0) {
        vr = __ldg(in_re + idx + S5);
        vi = __ldg(in_im + idx + S5);
    } else if (d5 == 1) {
        vr = __ldg(in_re + idx - S5);
        vi = __ldg(in_im + idx - S5);
    } else {
        vr = 0.0f; vi = 0.0f;
    }
    out_re[idx] = vr;
    out_im[idx] = vi;
}

__global__ void __launch_bounds__(256)
sx_apply_v4(const float* __restrict__ in_re,
            const float* __restrict__ in_im,
            float* __restrict__ out_re,
            float* __restrict__ out_im,   // only 4B-aligned! scalar stores only
            int n, int nq)
{
    int q = blockIdx.x * blockDim.x + threadIdx.x;
    if (q >= nq) return;
    int i = q << 2;

    int q5 = i / S5;                 // magic-mul divide
    int r5 = i - q5 * S5;
    int d5 = q5 % 3;
    int d2 = (q5 / 27) % 3;

    bool fast = (i + 4 <= n) && (r5 + 4 <= S5);

    if (fast) {
        const float4* in_re4  = reinterpret_cast<const float4*>(in_re);
        const float4* in_im4  = reinterpret_cast<const float4*>(in_im);
        float4*       out_re4 = reinterpret_cast<float4*>(out_re);

        float4 vr, vi;
        if (d2 != 1) {
            vr = __ldg(in_re4 + q);          // LDG.128
            vi = __ldg(in_im4 + q);          // LDG.128
        } else if (d5 == 2) {
            vr = make_float4(0.f, 0.f, 0.f, 0.f);
            vi = vr;
        } else {
            int s = (d5 == 0) ? (i + S5) : (i - S5);  // odd offset -> scalar gather
            vr.x = __ldg(in_re + s + 0);
            vr.y = __ldg(in_re + s + 1);
            vr.z = __ldg(in_re + s + 2);
            vr.w = __ldg(in_re + s + 3);
            vi.x = __ldg(in_im + s + 0);
            vi.y = __ldg(in_im + s + 1);
            vi.z = __ldg(in_im + s + 2);
            vi.w = __ldg(in_im + s + 3);
        }
        out_re4[q] = vr;                     // STG.128 (aligned)
        out_im[i + 0] = vi.x;                // 4x STG.32 (out_im is 4B-aligned)
        out_im[i + 1] = vi.y;
        out_im[i + 2] = vi.z;
        out_im[i + 3] = vi.w;
    } else {
        #pragma unroll
        for (int j = 0; j < 4; j++) {
            int idx = i + j;
            if (idx < n)
                scalar_one(in_re, in_im, out_re, out_im, idx);
        }
    }
}

extern "C" void kernel_launch(void* const* d_in, const int* in_sizes, int n_in,
                              void* d_out, int out_size)
{
    const float* in_re = (const float*)d_in[0];
    const float* in_im = (const float*)d_in[1];
    const int n = in_sizes[0];          // 3^16 = 43,046,721 (odd!)

    float* out_re = (float*)d_out;
    float* out_im = (float*)d_out + n;  // 4B-aligned only

    const int nq = (n + 3) >> 2;
    const int threads = 256;
    const int blocks = (nq + threads - 1) / threads;
    sx_apply_v4<<<blocks, threads>>>(in_re, in_im, out_re, out_im, n, nq);
}